// round 4
// baseline (speedup 1.0000x reference)
#include <cuda_runtime.h>
#include <stdint.h>

#define N_PTS   50000
#define B_ROWS  512
#define E_DIM   16
#define KSEL    20
#define TILE    512
#define BTHR    256
#define G_ROWS  8
#define SPLITS  2
#define NGRP    (B_ROWS / G_ROWS)
#define NBLK    (NGRP * 2 * SPLITS)
#define HID     64
#define FULLM   0xffffffffu

typedef unsigned long long ull;

__device__ float g_feats[B_ROWS][8];
__device__ float g_pval[2][NGRP][SPLITS][G_ROWS][KSEL];
__device__ int   g_pidx[2][NGRP][SPLITS][G_ROWS][KSEL];
__device__ int   g_flag[2][NGRP];
__device__ int   g_done = 0;

static __device__ __forceinline__ float finf() { return __int_as_float(0x7f800000); }

static __device__ __forceinline__ ull pk2(float lo, float hi) {
    ull r; asm("mov.b64 %0,{%1,%2};" : "=l"(r) : "f"(lo), "f"(hi)); return r;
}
static __device__ __forceinline__ void upk2(ull v, float& lo, float& hi) {
    asm("mov.b64 {%0,%1},%2;" : "=f"(lo), "=f"(hi) : "l"(v));
}
static __device__ __forceinline__ ull fma2(ull a, ull b, ull c) {
    ull d; asm("fma.rn.f32x2 %0,%1,%2,%3;" : "=l"(d) : "l"(a), "l"(b), "l"(c)); return d;
}
static __device__ __forceinline__ ull add2(ull a, ull b) {
    ull d; asm("add.rn.f32x2 %0,%1,%2;" : "=l"(d) : "l"(a), "l"(b)); return d;
}

__global__ __launch_bounds__(BTHR, 2)
void knn_kernel(const float* __restrict__ emb0, const float* __restrict__ emb1,
                const float* __restrict__ rctx0, const float* __restrict__ rctx1,
                const int* __restrict__ idx0, const int* __restrict__ idx1,
                const float* __restrict__ mean_in, const float* __restrict__ std_in,
                const float* __restrict__ W1, const float* __restrict__ b1,
                const float* __restrict__ Wm, const float* __restrict__ bm,
                const float* __restrict__ Ws, const float* __restrict__ bs,
                float* __restrict__ out, int n) {
    const int grp   = blockIdx.x;
    const int set   = blockIdx.y;
    const int split = blockIdx.z;
    const float* __restrict__ emb  = set ? emb1 : emb0;
    const float* __restrict__ rctx = set ? rctx1 : rctx0;
    const int*   __restrict__ idxp = set ? idx1 : idx0;

    const int rowbase = grp * G_ROWS;
    const int tid  = threadIdx.x;
    const int lane = tid & 31;
    const int w    = tid >> 5;

    __shared__ __align__(16) ull q_sm[8][8];
    __shared__ float na_sm[8];
    __shared__ int   self_sm[8];
    __shared__ float sbuf[2][TILE][9];
    __shared__ int   smflag[2];

    if (w < G_ROWS) {
        int si = 0;
        if (lane == 0) si = idxp[rowbase + w];
        si = __shfl_sync(FULLM, si, 0);
        if (lane == 0) self_sm[w] = si;
        float nx = 0.f;
        if (lane < 8) {
            float2 v = reinterpret_cast<const float2*>(emb + (size_t)si * E_DIM)[lane];
            nx = v.x * v.x + v.y * v.y;
            q_sm[lane][w] = pk2(-2.f * v.x, -2.f * v.y);
        }
        nx += __shfl_xor_sync(FULLM, nx, 4);
        nx += __shfl_xor_sync(FULLM, nx, 2);
        nx += __shfl_xor_sync(FULLM, nx, 1);
        if (lane == 0) na_sm[w] = nx;
    }
    __syncthreads();
    const int   selfi = self_sm[w];
    const float na    = na_sm[w];

    const int halfn = (n + SPLITS - 1) / SPLITS;
    const int jbeg  = split * halfn;
    const int jend  = min(n, jbeg + halfn);
    const int ntiles = (jend - jbeg + TILE - 1) / TILE;

    float kval   = finf();
    int   kidx   = -1;
    float thresh = finf();

    auto insert = [&](float bv, int bj) {
        float pv = __shfl_up_sync(FULLM, kval, 1);
        int   pj = __shfl_up_sync(FULLM, kidx, 1);
        if (lane < KSEL && bv < kval) {
            if (lane == 0 || bv >= pv) { kval = bv; kidx = bj; }
            else                        { kval = pv; kidx = pj; }
        }
        thresh = __shfl_sync(FULLM, kval, KSEL - 1);
    };

    auto phaseB = [&](int t) {
        const int buf  = t & 1;
        const int base = jbeg + t * TILE;
        float v[16];
#pragma unroll
        for (int i = 0; i < 16; i++) v[i] = sbuf[buf][lane + 32 * i][w];
        unsigned hm = 0;
#pragma unroll
        for (int i = 0; i < 16; i++) {
            int j = base + lane + 32 * i;
            if (v[i] < thresh && j != selfi) hm |= (1u << i);
        }
        unsigned red = __reduce_or_sync(FULLM, hm);
        while (red) {
            int i = __ffs(red) - 1; red &= red - 1;
            unsigned m = __ballot_sync(FULLM, (hm >> i) & 1u);
            float vi = v[i];
            int   ji = base + lane + 32 * i;
            while (m) {
                int src = __ffs(m) - 1; m &= m - 1;
                float bv = __shfl_sync(FULLM, vi, src);
                int   bj = __shfl_sync(FULLM, ji, src);
                if (bv < thresh) insert(bv, bj);
            }
        }
    };

    for (int t = 0; t < ntiles; t++) {
        const int j0 = jbeg + t * TILE + tid;
        const int j1 = j0 + BTHR;
        const bool v0 = (j0 < jend), v1 = (j1 < jend);
        ull e0[8], e1[8];
        if (v0) {
            const ulonglong2* p = reinterpret_cast<const ulonglong2*>(emb + (size_t)j0 * E_DIM);
            ulonglong2 a = p[0], b = p[1], c = p[2], d = p[3];
            e0[0]=a.x; e0[1]=a.y; e0[2]=b.x; e0[3]=b.y; e0[4]=c.x; e0[5]=c.y; e0[6]=d.x; e0[7]=d.y;
        }
        if (v1) {
            const ulonglong2* p = reinterpret_cast<const ulonglong2*>(emb + (size_t)j1 * E_DIM);
            ulonglong2 a = p[0], b = p[1], c = p[2], d = p[3];
            e1[0]=a.x; e1[1]=a.y; e1[2]=b.x; e1[3]=b.y; e1[4]=c.x; e1[5]=c.y; e1[6]=d.x; e1[7]=d.y;
        }

        if (t > 0) phaseB(t - 1);

        const int buf = t & 1;
        ull n0A = pk2(0.f, 0.f), n0B = pk2(0.f, 0.f);
        ull n1A = pk2(0.f, 0.f), n1B = pk2(0.f, 0.f);
#pragma unroll
        for (int c = 0; c < 8; c += 2) {
            n0A = fma2(e0[c], e0[c], n0A);   n0B = fma2(e0[c+1], e0[c+1], n0B);
            n1A = fma2(e1[c], e1[c], n1A);   n1B = fma2(e1[c+1], e1[c+1], n1B);
        }
        ull nrm0 = add2(n0A, n0B), nrm1 = add2(n1A, n1B);
        ull acc0[8], acc1[8];
#pragma unroll
        for (int r = 0; r < 8; r++) { acc0[r] = nrm0; acc1[r] = nrm1; }
#pragma unroll
        for (int c = 0; c < 8; c++) {
            const ulonglong2* qp = reinterpret_cast<const ulonglong2*>(&q_sm[c][0]);
#pragma unroll
            for (int p = 0; p < 4; p++) {
                ulonglong2 qv = qp[p];
                acc0[2*p]   = fma2(qv.x, e0[c], acc0[2*p]);
                acc0[2*p+1] = fma2(qv.y, e0[c], acc0[2*p+1]);
                acc1[2*p]   = fma2(qv.x, e1[c], acc1[2*p]);
                acc1[2*p+1] = fma2(qv.y, e1[c], acc1[2*p+1]);
            }
        }
#pragma unroll
        for (int r = 0; r < 8; r++) {
            float lo, hi;
            upk2(acc0[r], lo, hi);
            sbuf[buf][tid][r]        = v0 ? (lo + hi) : finf();
            upk2(acc1[r], lo, hi);
            sbuf[buf][tid + BTHR][r] = v1 ? (lo + hi) : finf();
        }
        __syncthreads();
    }
    phaseB(ntiles - 1);

    // ---- split rendezvous: per-split partial slots ----
    if (lane < KSEL) {
        g_pval[set][grp][split][w][lane] = kval;
        g_pidx[set][grp][split][w][lane] = kidx;
    }
    __threadfence();
    __syncthreads();
    if (tid == 0) smflag[0] = atomicAdd(&g_flag[set][grp], 1);
    __syncthreads();

    if (smflag[0] == 1) {               // second arrival: merge partner slot
        __threadfence();
        const int po = 1 - split;
        for (int i = 0; i < KSEL; i++) {
            float bv = g_pval[set][grp][po][w][i];
            int   bj = g_pidx[set][grp][po][w][i];
            if (bv < thresh) insert(bv, bj);
        }
        const int row = rowbase + w;
        float wgt = 0.f, sel = 0.f;
        if (lane < KSEL) {
            float d2  = fmaxf(kval + na, 0.f);
            float sim = sqrtf(d2) + 0.001f;
            wgt = __expf(-sim);
            sel = rctx[(size_t)row * n + kidx];
        }
        float sw = wgt, ssw = sel * wgt, ss = sel, ss2 = sel * sel;
#pragma unroll
        for (int off = 16; off; off >>= 1) {
            sw  += __shfl_xor_sync(FULLM, sw,  off);
            ssw += __shfl_xor_sync(FULLM, ssw, off);
            ss  += __shfl_xor_sync(FULLM, ss,  off);
            ss2 += __shfl_xor_sync(FULLM, ss2, off);
        }
        if (lane == 0) {
            g_feats[row][0 + set] = sw;
            g_feats[row][2 + set] = ssw / sw;
            float var = (ss2 - ss * ss / (float)KSEL) / (float)(KSEL - 1);
            g_feats[row][4 + set] = sqrtf(fmaxf(var, 0.f));
        }
        if (tid == 0) g_flag[set][grp] = 0;
    }

    // ---- global tail: MLP ----
    __threadfence();
    __syncthreads();
    if (tid == 0) smflag[1] = atomicAdd(&g_done, 1);
    __syncthreads();
    if (smflag[1] != NBLK - 1) return;
    __threadfence();

#pragma unroll
    for (int rr = 0; rr < 2; rr++) {
        int r = tid + BTHR * rr;
        float f[8];
#pragma unroll
        for (int i = 0; i < 6; i++) f[i] = g_feats[r][i];
        f[6] = mean_in[r];
        f[7] = std_in[r];
        float m = bm[0], sd = bs[0];
#pragma unroll 4
        for (int j = 0; j < HID; j++) {
            float h = b1[j];
#pragma unroll
            for (int i = 0; i < 8; i++) h = fmaf(f[i], W1[i * HID + j], h);
            h = fmaxf(h, 0.f);
            m  = fmaf(h, Wm[j], m);
            sd = fmaf(h, Ws[j], sd);
        }
        out[r]          = m;
        out[B_ROWS + r] = sd;
    }
    if (tid == 0) g_done = 0;
}

extern "C" void kernel_launch(void* const* d_in, const int* in_sizes, int n_in,
                              void* d_out, int out_size) {
    const float* emb0    = (const float*)d_in[0];
    const float* emb1    = (const float*)d_in[1];
    const float* rctx0   = (const float*)d_in[2];
    const float* rctx1   = (const float*)d_in[3];
    const int*   idx0    = (const int*)  d_in[4];
    const int*   idx1    = (const int*)  d_in[5];
    const float* mean_in = (const float*)d_in[6];
    const float* std_in  = (const float*)d_in[7];
    const float* W1      = (const float*)d_in[8];
    const float* b1      = (const float*)d_in[9];
    const float* Wm      = (const float*)d_in[10];
    const float* bm      = (const float*)d_in[11];
    const float* Ws      = (const float*)d_in[12];
    const float* bs      = (const float*)d_in[13];

    int n = in_sizes[0] / E_DIM;

    dim3 grid(NGRP, 2, SPLITS);
    knn_kernel<<<grid, BTHR>>>(emb0, emb1, rctx0, rctx1, idx0, idx1,
                               mean_in, std_in, W1, b1, Wm, bm, Ws, bs,
                               (float*)d_out, n);
}